// round 17
// baseline (speedup 1.0000x reference)
#include <cuda_runtime.h>
#include <cuda_fp16.h>
#include <math.h>
#include <stdint.h>

#define BB 32
#define TT 2048
#define EE 1024
#define MTOT (BB * TT)   // 65536

// lo-parts are pre-scaled by 2^11 at split time; undone in the epilogue
#define LO_SCALE 2048.0f
#define LO_INV   (1.0f / 2048.0f)

// ---------------- device scratch ----------------
__device__ __half g_ht[(size_t)MTOT * EE];        // 128 MB, tanh(enc@W+b) fp16
__device__ float g_scores[MTOT];
__device__ __half g_Ahi[(size_t)MTOT * EE];       // 128 MB
__device__ __half g_Alo[(size_t)MTOT * EE];       // 128 MB (x 2^11)
__device__ __half g_Bhi[(size_t)EE * EE];         // Wt hi (N,K)
__device__ __half g_Blo[(size_t)EE * EE];         // Wt lo (N,K) (x 2^11)

// ---------------- helpers ----------------
__device__ __forceinline__ uint32_t smem_u32(const void* p) {
    uint32_t a;
    asm("{ .reg .u64 t; cvta.to.shared.u64 t, %1; cvt.u32.u64 %0, t; }"
        : "=r"(a) : "l"(p));
    return a;
}

__device__ __forceinline__ void cpasync16(uint32_t smem_dst, const void* gptr) {
    asm volatile("cp.async.cg.shared.global [%0], [%1], 16;"
                 :: "r"(smem_dst), "l"(gptr) : "memory");
}

__device__ __forceinline__ void ldsm4(uint32_t* r, uint32_t addr) {
    asm volatile("ldmatrix.sync.aligned.m8n8.x4.shared.b16 {%0,%1,%2,%3}, [%4];"
                 : "=r"(r[0]), "=r"(r[1]), "=r"(r[2]), "=r"(r[3]) : "r"(addr));
}

// fp32-accumulator fp16 MMA (main term)
__device__ __forceinline__ void mma16816(float* c, const uint32_t* a, const uint32_t* b) {
    asm volatile("mma.sync.aligned.m16n8k16.row.col.f32.f16.f16.f32 "
                 "{%0,%1,%2,%3}, {%4,%5,%6,%7}, {%8,%9}, {%0,%1,%2,%3};"
                 : "+f"(c[0]), "+f"(c[1]), "+f"(c[2]), "+f"(c[3])
                 : "r"(a[0]), "r"(a[1]), "r"(a[2]), "r"(a[3]),
                   "r"(b[0]), "r"(b[1]));
}

// fp16-accumulator fp16 MMA (correction terms)
__device__ __forceinline__ void mma16816h(uint32_t* c, const uint32_t* a, const uint32_t* b) {
    asm volatile("mma.sync.aligned.m16n8k16.row.col.f16.f16.f16.f16 "
                 "{%0,%1}, {%2,%3,%4,%5}, {%6,%7}, {%0,%1};"
                 : "+r"(c[0]), "+r"(c[1])
                 : "r"(a[0]), "r"(a[1]), "r"(a[2]), "r"(a[3]),
                   "r"(b[0]), "r"(b[1]));
}

__device__ __forceinline__ uint32_t packh2(float x, float y) {
    __half2 h = __floats2half2_rn(x, y);
    return *(uint32_t*)&h;
}

// ---------------- GEMM config ----------------
#define MT 128
#define NT 64
#define BK 64                                   // k elems per chunk (128 B rows)
#define NCHUNK (EE / BK)                        // 16
#define OFF_AHI 0
#define OFF_ALO (MT * BK * 2)                   // 16384
#define OFF_BHI (2 * MT * BK * 2)               // 32768
#define OFF_BLO (2 * MT * BK * 2 + NT * BK * 2) // 40960
#define STAGE_BYTES (2 * MT * BK * 2 + 2 * NT * BK * 2)  // 49152
#define DSM_BYTES (2 * STAGE_BYTES)             // 98304 per CTA (2 CTAs/SM)

// ---------------- prepass: split enc into fp16 hi + scaled lo (+ zero scores) --
// Each thread: 8 floats (two float4 loads) -> one uint4 store to Ahi, one to Alo.
__global__ void __launch_bounds__(256) split_enc_kernel(const float* __restrict__ A)
{
    // fold scores zeroing into the first 256 blocks (grid = 32768 blocks)
    if (blockIdx.x < MTOT / 256)
        g_scores[blockIdx.x * 256 + threadIdx.x] = 0.0f;

    size_t i = ((size_t)blockIdx.x * 256 + threadIdx.x) * 8;
    float4 v0 = *(const float4*)(A + i);
    float4 v1 = *(const float4*)(A + i + 4);

    uint4 hh, ll;
    hh.x = packh2(v0.x, v0.y);
    hh.y = packh2(v0.z, v0.w);
    hh.z = packh2(v1.x, v1.y);
    hh.w = packh2(v1.z, v1.w);

    float2 b0 = __half22float2(*(__half2*)&hh.x);
    float2 b1 = __half22float2(*(__half2*)&hh.y);
    float2 b2 = __half22float2(*(__half2*)&hh.z);
    float2 b3 = __half22float2(*(__half2*)&hh.w);
    ll.x = packh2((v0.x - b0.x) * LO_SCALE, (v0.y - b0.y) * LO_SCALE);
    ll.y = packh2((v0.z - b1.x) * LO_SCALE, (v0.w - b1.y) * LO_SCALE);
    ll.z = packh2((v1.x - b2.x) * LO_SCALE, (v1.y - b2.y) * LO_SCALE);
    ll.w = packh2((v1.z - b3.x) * LO_SCALE, (v1.w - b3.y) * LO_SCALE);

    *(uint4*)(g_Ahi + i) = hh;
    *(uint4*)(g_Alo + i) = ll;
}

// ---------------- prepass: transpose + split W -> Wt[n][k] fp16 hi + scaled lo --
__global__ void __launch_bounds__(256) splitW_kernel(const float* __restrict__ W)
{
    __shared__ float tile[32][33];
    int n0 = blockIdx.x * 32, k0 = blockIdx.y * 32;
    int tx = threadIdx.x & 31, ty = threadIdx.x >> 5;  // 32 x 8
#pragma unroll
    for (int r = 0; r < 4; r++)
        tile[ty + 8 * r][tx] = W[(size_t)(k0 + ty + 8 * r) * EE + n0 + tx];
    __syncthreads();
#pragma unroll
    for (int r = 0; r < 4; r++) {
        int ny = ty + 8 * r;
        float v = tile[tx][ny];
        __half h = __float2half_rn(v);
        __half l = __float2half_rn((v - __half2float(h)) * LO_SCALE);
        size_t o = (size_t)(n0 + ny) * EE + k0 + tx;
        g_Bhi[o] = h;
        g_Blo[o] = l;
    }
}

// ---------------- fused GEMM + bias + tanh + scores ----------------
__device__ __forceinline__ void load_chunk(int c, uint32_t sm0, size_t m0, int n0, int tid)
{
    uint32_t sb = sm0 + (uint32_t)(c & 1) * STAGE_BYTES;
    int k0 = c * BK;
    const __half* Ahi = g_Ahi + m0 * EE + k0;
    const __half* Alo = g_Alo + m0 * EE + k0;
    const __half* Bhi = g_Bhi + (size_t)n0 * EE + k0;
    const __half* Blo = g_Blo + (size_t)n0 * EE + k0;
#pragma unroll
    for (int i = 0; i < 4; i++) {           // A: 128 rows x 8 granules(16B)
        int idx = tid + i * 256;
        int row = idx >> 3, j = idx & 7;
        uint32_t d = sb + (uint32_t)(row * 128 + ((j ^ (row & 7)) << 4));
        const size_t go = (size_t)row * EE + j * 8;
        cpasync16(d + OFF_AHI, Ahi + go);
        cpasync16(d + OFF_ALO, Alo + go);
    }
#pragma unroll
    for (int i = 0; i < 2; i++) {           // B: 64 rows x 8 granules(16B)
        int idx = tid + i * 256;
        int row = idx >> 3, j = idx & 7;
        uint32_t d = sb + (uint32_t)(row * 128 + ((j ^ (row & 7)) << 4));
        const size_t go = (size_t)row * EE + j * 8;
        cpasync16(d + OFF_BHI, Bhi + go);
        cpasync16(d + OFF_BLO, Blo + go);
    }
    asm volatile("cp.async.commit_group;" ::: "memory");
}

__device__ __forceinline__ uint32_t a_frag_addr(uint32_t base, int row0, int t, int lane) {
    int r = row0 + (lane & 15);
    int j = t * 2 + (lane >> 4);
    return base + (uint32_t)(r * 128 + ((j ^ (r & 7)) << 4));
}
__device__ __forceinline__ uint32_t b_frag_addr(uint32_t base, int n0, int t, int lane) {
    int r = n0 + (lane & 7) + ((lane & 16) >> 1);
    int j = t * 2 + ((lane >> 3) & 1);
    return base + (uint32_t)(r * 128 + ((j ^ (r & 7)) << 4));
}

__global__ void __launch_bounds__(256, 2) gemm_hmma_kernel(
    const float* __restrict__ ctx,
    const float* __restrict__ bias)
{
    extern __shared__ __align__(1024) char dsm_raw[];
    uint32_t sm0 = smem_u32(dsm_raw);

    __shared__ float s_bias[NT];
    __shared__ float s_ctx[NT];

    const int tid = threadIdx.x;
    const int wid = tid >> 5, lane = tid & 31;
    const int warp_m = wid & 3;              // 0..3 (32-row slabs)
    const int warp_n = wid >> 2;             // 0..1 (32-col slabs)
    const int n0c = blockIdx.x * NT;
    const size_t m0 = (size_t)blockIdx.y * MT;
    const int bidx = (int)(m0 / TT);

    if (tid < NT) {
        s_bias[tid] = bias[n0c + tid];
        s_ctx[tid]  = ctx[bidx * EE + n0c + tid];
    }

    float acc[2][4][4];                      // main term, fp32
    uint32_t ach[2][4][2];                   // correction terms, fp16x2 (x 2^11)
#pragma unroll
    for (int mi = 0; mi < 2; mi++)
#pragma unroll
        for (int ni = 0; ni < 4; ni++) {
#pragma unroll
            for (int e = 0; e < 4; e++) acc[mi][ni][e] = 0.0f;
            ach[mi][ni][0] = 0u;
            ach[mi][ni][1] = 0u;
        }

    load_chunk(0, sm0, m0, n0c, tid);

    for (int c = 0; c < NCHUNK; c++) {
        asm volatile("cp.async.wait_group 0;" ::: "memory");
        __syncthreads();
        // prefetch next chunk into the buffer everyone just finished reading
        if (c + 1 < NCHUNK) load_chunk(c + 1, sm0, m0, n0c, tid);

        const uint32_t sb   = sm0 + (uint32_t)(c & 1) * STAGE_BYTES;
        const uint32_t sAhi = sb + OFF_AHI;
        const uint32_t sAlo = sb + OFF_ALO;
        const uint32_t sBhi = sb + OFF_BHI;
        const uint32_t sBlo = sb + OFF_BLO;

#pragma unroll
        for (int t = 0; t < 4; t++) {       // 4 k16 steps per BK=64
            uint32_t bh[2][4], bl[2][4], af[2][4], al[2][4];
#pragma unroll
            for (int np = 0; np < 2; np++) {
                ldsm4(bh[np], b_frag_addr(sBhi, warp_n * 32 + np * 16, t, lane));
                ldsm4(bl[np], b_frag_addr(sBlo, warp_n * 32 + np * 16, t, lane));
            }
#pragma unroll
            for (int mi = 0; mi < 2; mi++) {
                ldsm4(af[mi], a_frag_addr(sAhi, warp_m * 32 + mi * 16, t, lane));
                ldsm4(al[mi], a_frag_addr(sAlo, warp_m * 32 + mi * 16, t, lane));
            }
#pragma unroll
            for (int mi = 0; mi < 2; mi++)
#pragma unroll
                for (int ni = 0; ni < 4; ni++)
                    mma16816(acc[mi][ni], af[mi], &bh[ni >> 1][(ni & 1) * 2]);
#pragma unroll
            for (int mi = 0; mi < 2; mi++)
#pragma unroll
                for (int ni = 0; ni < 4; ni++)
                    mma16816h(ach[mi][ni], af[mi], &bl[ni >> 1][(ni & 1) * 2]);
#pragma unroll
            for (int mi = 0; mi < 2; mi++)
#pragma unroll
                for (int ni = 0; ni < 4; ni++)
                    mma16816h(ach[mi][ni], al[mi], &bh[ni >> 1][(ni & 1) * 2]);
        }
    }

    // epilogue: main + 2^-11 * corrections + bias, tanh, fp16 ht store, fused scores
    const int lr = lane >> 2;               // 0..7
    const int lc = (lane & 3) * 2;
    const int tbase = (int)(m0 % TT) + warp_m * 32;
#pragma unroll
    for (int mi = 0; mi < 2; mi++) {
        const size_t row0 = m0 + (size_t)(warp_m * 32 + mi * 16 + lr);
        float rs0 = 0.0f, rs1 = 0.0f;
#pragma unroll
        for (int ni = 0; ni < 4; ni++) {
            const int col = warp_n * 32 + ni * 8 + lc;
            const float b0 = s_bias[col], b1 = s_bias[col + 1];
            const float c0 = s_ctx[col],  c1 = s_ctx[col + 1];
            float2 cr0 = __half22float2(*(__half2*)&ach[mi][ni][0]);
            float2 cr1 = __half22float2(*(__half2*)&ach[mi][ni][1]);
            float2 v0, v1;
            v0.x = tanhf(acc[mi][ni][0] + LO_INV * cr0.x + b0);
            v0.y = tanhf(acc[mi][ni][1] + LO_INV * cr0.y + b1);
            v1.x = tanhf(acc[mi][ni][2] + LO_INV * cr1.x + b0);
            v1.y = tanhf(acc[mi][ni][3] + LO_INV * cr1.y + b1);
            *(__half2*)(g_ht + row0 * EE + n0c + col) = __float22half2_rn(v0);
            *(__half2*)(g_ht + (row0 + 8) * EE + n0c + col) = __float22half2_rn(v1);
            rs0 += v0.x * c0 + v0.y * c1;
            rs1 += v1.x * c0 + v1.y * c1;
        }
        rs0 += __shfl_xor_sync(0xffffffffu, rs0, 1);
        rs0 += __shfl_xor_sync(0xffffffffu, rs0, 2);
        rs1 += __shfl_xor_sync(0xffffffffu, rs1, 1);
        rs1 += __shfl_xor_sync(0xffffffffu, rs1, 2);
        if ((lane & 3) == 0) {
            atomicAdd(&g_scores[bidx * TT + tbase + mi * 16 + lr], rs0);
            atomicAdd(&g_scores[bidx * TT + tbase + mi * 16 + lr + 8], rs1);
        }
    }
}

// ---------------- fused softmax + pool ----------------
// Each block: recompute softmax normalizers over the batch's TT scores (8 KB),
// build at for its 128 timesteps, accumulate out columns.
// Each thread owns 8 columns (one uint4 = 16 B per row); 128 threads cover a
// full 2 KB row, and the block's two halves process even/odd rows.
__global__ void __launch_bounds__(256) pool_kernel(float* __restrict__ out)
{
    __shared__ float red[256];
    __shared__ float ats[128];
    const int b = blockIdx.z;
    const int tid = threadIdx.x;
    const int half = tid >> 7;               // 0: even rows, 1: odd rows
    const int e = (tid & 127) * 8;            // 8 half columns
    const int t0 = blockIdx.y * 128;

    // softmax normalizers over the full row of scores
    float v[8];
    float m = -1e30f;
#pragma unroll
    for (int i = 0; i < 8; i++) {
        v[i] = g_scores[b * TT + tid + i * 256];
        m = fmaxf(m, v[i]);
    }
    red[tid] = m;
    __syncthreads();
#pragma unroll
    for (int s = 128; s > 0; s >>= 1) {
        if (tid < s) red[tid] = fmaxf(red[tid], red[tid + s]);
        __syncthreads();
    }
    const float mx = red[0];
    __syncthreads();

    float sum = 0.0f;
#pragma unroll
    for (int i = 0; i < 8; i++)
        sum += expf(v[i] - mx);
    red[tid] = sum;
    __syncthreads();
#pragma unroll
    for (int s = 128; s > 0; s >>= 1) {
        if (tid < s) red[tid] += red[tid + s];
        __syncthreads();
    }
    const float inv = 1.0f / red[0];

    // local at values for this block's 128 timesteps
    if (tid < 128)
        ats[tid] = expf(g_scores[b * TT + t0 + tid] - mx) * inv;
    __syncthreads();

    // rows t0+half, t0+half+2, ... (64 rows per thread), 16 B per row
    const __half* hp0 = g_ht + ((size_t)(b * TT + t0 + half)) * EE + e;
    float a0 = 0.0f, a1 = 0.0f, a2 = 0.0f, a3 = 0.0f;
    float a4 = 0.0f, a5 = 0.0f, a6 = 0.0f, a7 = 0.0f;
#pragma unroll 8
    for (int i = 0; i < 64; i++) {
        uint4 u = *(const uint4*)(hp0 + (size_t)i * 2 * EE);
        float2 h0 = __half22float2(*(__half2*)&u.x);
        float2 h1 = __half22float2(*(__half2*)&u.y);
        float2 h2 = __half22float2(*(__half2*)&u.z);
        float2 h3 = __half22float2(*(__half2*)&u.w);
        const float w = ats[i * 2 + half];
        a0 += w * h0.x;  a1 += w * h0.y;
        a2 += w * h1.x;  a3 += w * h1.y;
        a4 += w * h2.x;  a5 += w * h2.y;
        a6 += w * h3.x;  a7 += w * h3.y;
    }
    atomicAdd(&out[b * EE + e + 0], a0);
    atomicAdd(&out[b * EE + e + 1], a1);
    atomicAdd(&out[b * EE + e + 2], a2);
    atomicAdd(&out[b * EE + e + 3], a3);
    atomicAdd(&out[b * EE + e + 4], a4);
    atomicAdd(&out[b * EE + e + 5], a5);
    atomicAdd(&out[b * EE + e + 6], a6);
    atomicAdd(&out[b * EE + e + 7], a7);
}

// ---------------- launch ----------------
extern "C" void kernel_launch(void* const* d_in, const int* in_sizes, int n_in,
                              void* d_out, int out_size)
{
    const float* enc  = (const float*)d_in[0];   // (B, T, E)
    const float* ctx  = (const float*)d_in[1];   // (B, E)
    const float* Wm   = (const float*)d_in[2];   // (E, E)
    const float* bias = (const float*)d_in[3];   // (1, E)
    float* out = (float*)d_out;                  // (B, E)

    cudaFuncSetAttribute(gemm_hmma_kernel,
                         cudaFuncAttributeMaxDynamicSharedMemorySize, DSM_BYTES);

    cudaMemsetAsync(out, 0, sizeof(float) * BB * EE);

    split_enc_kernel<<<(size_t)MTOT * EE / 2048, 256>>>(enc);
    splitW_kernel<<<dim3(EE / 32, EE / 32), 256>>>(Wm);
    gemm_hmma_kernel<<<dim3(EE / NT, MTOT / MT), 256, DSM_BYTES>>>(ctx, bias);
    pool_kernel<<<dim3(1, TT / 128, BB), 256>>>(out);
}